// round 2
// baseline (speedup 1.0000x reference)
#include <cuda_runtime.h>

#define BB 32
#define TT 4096
#define DX 128
#define HH 128
#define GG 384       // 3*H
#define NK 10
#define NROWS (BB*TT)   // 131072

// Scratch: input projections [t*B+b][768] (fwd gates 0..383, bwd 384..767)
__device__ float g_xp[(size_t)NROWS * 768];
// Hidden states concatenated [b*T+t][256] (fwd 0..127, bwd 128..255)
__device__ float g_h[(size_t)NROWS * 256];

// Packed dual fp32 FMA (sm_103a): d.lo += a.lo*b.lo ; d.hi += a.hi*b.hi
#define FFMA2(acc, aa, bb) \
    asm("fma.rn.f32x2 %0, %1, %2, %0;" : "+l"(acc) : "l"(aa), "l"(bb))

__device__ __forceinline__ float f_lo(unsigned long long v) { return __uint_as_float((unsigned)v); }
__device__ __forceinline__ float f_hi(unsigned long long v) { return __uint_as_float((unsigned)(v >> 32)); }

// 128-dot of SMEM vector (broadcast) against 64 packed u64 register weights.
// Software-pipelined LDS (distance-2, 16B groups) + 4 independent FMA chains:
// keeps the fma pipe fed instead of exposing the 29-cyc LDS latency per use.
__device__ __forceinline__ float dot128(const float* __restrict__ hsm,
                                        const unsigned long long (&w)[64]) {
    const ulonglong2* hs = (const ulonglong2*)hsm;
    unsigned long long a0 = 0ull, a1 = 0ull, a2 = 0ull, a3 = 0ull;
    ulonglong2 p0 = hs[0], p1 = hs[1];   // group 0 (k 0..7)
    ulonglong2 q0 = hs[2], q1 = hs[3];   // group 1 (k 8..15)
#pragma unroll
    for (int g = 0; g < 16; ++g) {
        ulonglong2 c0 = p0, c1 = p1;
        p0 = q0; p1 = q1;
        if (g + 2 < 16) { q0 = hs[2 * (g + 2)]; q1 = hs[2 * (g + 2) + 1]; }
        FFMA2(a0, c0.x, w[4 * g + 0]);
        FFMA2(a1, c0.y, w[4 * g + 1]);
        FFMA2(a2, c1.x, w[4 * g + 2]);
        FFMA2(a3, c1.y, w[4 * g + 3]);
    }
    float s0 = f_lo(a0) + f_hi(a0);
    float s1 = f_lo(a1) + f_hi(a1);
    float s2 = f_lo(a2) + f_hi(a2);
    float s3 = f_lo(a3) + f_hi(a3);
    return (s0 + s1) + (s2 + s3);
}

// ---------------------------------------------------------------------------
// Kernel 1: input projections xp = x @ W_ih^T + b_ih for both directions.
// One CTA = 384 threads = 384 gate columns of one direction; each thread keeps
// its 128 weights in registers. CTA streams rows (t,b).
// ---------------------------------------------------------------------------
__global__ __launch_bounds__(384, 1) void proj_kernel(
    const float* __restrict__ x,
    const float* __restrict__ Wf, const float* __restrict__ bf,
    const float* __restrict__ Wb, const float* __restrict__ bb)
{
    const int d = blockIdx.x / 74;   // 0 fwd, 1 bwd   (grid = 148)
    const int c = blockIdx.x % 74;
    const float* W  = d ? Wb : Wf;
    const float* bi = d ? bb : bf;
    const int j = threadIdx.x;

    unsigned long long w[64];
    const unsigned long long* wrow = (const unsigned long long*)(W + j * DX);
#pragma unroll
    for (int i = 0; i < 64; ++i) w[i] = wrow[i];
    const float bias = bi[j];

    __shared__ __align__(16) float xs[2][DX];

    const int chunk = (NROWS + 73) / 74;      // 1772
    const int r0 = c * chunk;
    const int r1 = min(r0 + chunk, NROWS);

    // prefetch first row (row r -> b = r&31, t = r>>5 ; x is [B,T,Dx])
    float xr = 0.f;
    if (j < DX) {
        int b0 = r0 & 31, t0 = r0 >> 5;
        xr = x[((size_t)(b0 * TT + t0)) * DX + j];
    }
    int p = 0;
    for (int r = r0; r < r1; ++r) {
        if (j < DX) {
            xs[p][j] = xr;
            if (r + 1 < r1) {
                int bn = (r + 1) & 31, tn = (r + 1) >> 5;
                xr = x[((size_t)(bn * TT + tn)) * DX + j];
            }
        }
        __syncthreads();
        const float acc = dot128(xs[p], w);
        g_xp[(size_t)r * 768 + d * GG + j] = acc + bias;
        p ^= 1;
    }
}

// ---------------------------------------------------------------------------
// Kernel 2: the sequential GRU scan. One CTA per (direction, batch) sequence:
// 64 CTAs. Thread j owns recurrent weight row j (registers). Per step:
//   dot over h (SMEM broadcast, pipelined) -> gate pre-acts -> barrier ->
//   threads 0..127 apply nonlinearities, update h, store to g_h -> barrier.
// ---------------------------------------------------------------------------
__global__ __launch_bounds__(384, 1) void scan_kernel(
    const float* __restrict__ Whf, const float* __restrict__ bhf,
    const float* __restrict__ Whb, const float* __restrict__ bhb)
{
    const int bx = blockIdx.x;          // 64
    const int d = bx >> 5;
    const int b = bx & 31;
    const float* W  = d ? Whb : Whf;
    const float* bh = d ? bhb : bhf;
    const int j = threadIdx.x;

    unsigned long long w[64];
    const unsigned long long* wrow = (const unsigned long long*)(W + j * HH);
#pragma unroll
    for (int i = 0; i < 64; ++i) w[i] = wrow[i];
    const float bias = bh[j];

    __shared__ __align__(16) float h_sh[HH];
    __shared__ float ga[GG];
    __shared__ float xn_sh[HH];

    if (j < HH) h_sh[j] = 0.f;
    __syncthreads();

    const int stride = BB * 768;                       // floats per timestep
    const int t0 = d ? (TT - 1) : 0;
    const float* xptr = g_xp + (size_t)(t0 * BB + b) * 768 + d * GG + j;
    const int dstep = d ? -stride : stride;

    float xv = __ldg(xptr);                            // prefetch t0
    float* hout = g_h + (size_t)(b * TT) * 256 + d * HH + j;  // used when j<128

    for (int tt = 0; tt < TT; ++tt) {
        const float xg = xv;
        if (tt + 1 < TT) xv = __ldg(xptr + dstep);     // prefetch next step
        xptr += dstep;

        const float hp = dot128(h_sh, w) + bias;       // h@Whh^T + bhh
        if (j < 2 * HH) {
            ga[j] = xg + hp;                           // r,z pre-activations
        } else {
            ga[j] = hp;                                // hn kept separate
            xn_sh[j - 2 * HH] = xg;                    // xn stashed
        }
        __syncthreads();

        if (j < HH) {
            const float r = 1.f / (1.f + __expf(-ga[j]));
            const float z = 1.f / (1.f + __expf(-ga[HH + j]));
            const float npre = xn_sh[j] + r * ga[2 * HH + j];
            const float e = __expf(2.f * npre);        // tanh = 1 - 2/(e+1)
            const float n = 1.f - __fdividef(2.f, e + 1.f);
            const float hnew = n + z * (h_sh[j] - n);  // (1-z)n + z h
            h_sh[j] = hnew;
            const int tcur = d ? (TT - 1 - tt) : tt;
            hout[(size_t)tcur * 256] = hnew;
        }
        __syncthreads();
    }
}

// ---------------------------------------------------------------------------
// Kernel 3: FC head out = hcat @ Wfc^T + bfc. Warp per row, lane-strided
// loads (coalesced), shfl reduction. Memory-bound (~134 MB).
// ---------------------------------------------------------------------------
__global__ __launch_bounds__(256) void fc_kernel(
    const float* __restrict__ Wfc, const float* __restrict__ bfc,
    float* __restrict__ out)
{
    __shared__ float Ws[NK * 256];
    __shared__ float bs[NK];
    for (int i = threadIdx.x; i < NK * 256; i += 256) Ws[i] = Wfc[i];
    if (threadIdx.x < NK) bs[threadIdx.x] = bfc[threadIdx.x];
    __syncthreads();

    const int gwarp = (blockIdx.x * 256 + threadIdx.x) >> 5;
    const int lane = threadIdx.x & 31;
    const int nwarps = gridDim.x * 8;

    for (int row = gwarp; row < NROWS; row += nwarps) {
        const float* hr = g_h + (size_t)row * 256;
        float hv[8];
#pragma unroll
        for (int m = 0; m < 8; ++m) hv[m] = hr[lane + 32 * m];
        float acc[NK];
#pragma unroll
        for (int k = 0; k < NK; ++k) {
            float s = 0.f;
#pragma unroll
            for (int m = 0; m < 8; ++m) s += hv[m] * Ws[k * 256 + lane + 32 * m];
            acc[k] = s;
        }
#pragma unroll
        for (int k = 0; k < NK; ++k) {
#pragma unroll
            for (int o = 16; o > 0; o >>= 1)
                acc[k] += __shfl_down_sync(0xffffffffu, acc[k], o);
        }
        if (lane == 0) {
#pragma unroll
            for (int k = 0; k < NK; ++k)
                out[(size_t)row * NK + k] = acc[k] + bs[k];
        }
    }
}

// ---------------------------------------------------------------------------
extern "C" void kernel_launch(void* const* d_in, const int* in_sizes, int n_in,
                              void* d_out, int out_size)
{
    const float* x    = (const float*)d_in[0];
    const float* Wihf = (const float*)d_in[1];
    const float* Whhf = (const float*)d_in[2];
    const float* bihf = (const float*)d_in[3];
    const float* bhhf = (const float*)d_in[4];
    const float* Wihb = (const float*)d_in[5];
    const float* Whhb = (const float*)d_in[6];
    const float* bihb = (const float*)d_in[7];
    const float* bhhb = (const float*)d_in[8];
    const float* Wfc  = (const float*)d_in[9];
    const float* bfc  = (const float*)d_in[10];
    float* out = (float*)d_out;

    proj_kernel<<<148, 384>>>(x, Wihf, bihf, Wihb, bihb);
    scan_kernel<<<64, 384>>>(Whhf, bhhf, Whhb, bhhb);
    fc_kernel<<<296, 256>>>(Wfc, bfc, out);
}

// round 3
// speedup vs baseline: 1.0938x; 1.0938x over previous
#include <cuda_runtime.h>

#define BB 32
#define TT 4096
#define DX 128
#define HH 128
#define GG 384       // 3*H
#define NK 10
#define NROWS (BB*TT)   // 131072

// Scratch: input projections [t*B+b][768] (fwd gates 0..383, bwd 384..767)
__device__ float g_xp[(size_t)NROWS * 768];
// Hidden states concatenated [b*T+t][256] (fwd 0..127, bwd 128..255)
__device__ float g_h[(size_t)NROWS * 256];

// Packed dual fp32 FMA (sm_103a): d.lo += a.lo*b.lo ; d.hi += a.hi*b.hi
#define FFMA2(acc, aa, bb) \
    asm("fma.rn.f32x2 %0, %1, %2, %0;" : "+l"(acc) : "l"(aa), "l"(bb))

__device__ __forceinline__ float f_lo(unsigned long long v) { return __uint_as_float((unsigned)v); }
__device__ __forceinline__ float f_hi(unsigned long long v) { return __uint_as_float((unsigned)(v >> 32)); }
__device__ __forceinline__ float usum(unsigned long long v) { return f_lo(v) + f_hi(v); }

// Padded vector layout: k-quarter s (32 floats) lives at float offset 36*s.
// Quarter bases hit banks {0,4,8,12}+4i -> the 4 lane-groups of a warp read
// disjoint banks: every LDS.128 is one conflict-free wavefront (64B useful).
#define QPAD 36

// Thread (j3 = tid>>2, s = tid&3), 512 threads: 3 outputs (3*j3..3*j3+2) over
// k-quarter s. 96 weight regs/thread, 8 LDS.128 per dot, 48 FFMA2 (3 chains).
struct WReg { unsigned long long w0[16], w1[16], w2[16]; };

__device__ __forceinline__ void load_weights(WReg& wr, const float* __restrict__ W,
                                             int j3, int s, int ldw) {
    const ulonglong2* r0 = (const ulonglong2*)(W + (3 * j3 + 0) * ldw + 32 * s);
    const ulonglong2* r1 = (const ulonglong2*)(W + (3 * j3 + 1) * ldw + 32 * s);
    const ulonglong2* r2 = (const ulonglong2*)(W + (3 * j3 + 2) * ldw + 32 * s);
#pragma unroll
    for (int i = 0; i < 8; ++i) {
        ulonglong2 a = r0[i]; wr.w0[2 * i] = a.x; wr.w0[2 * i + 1] = a.y;
        ulonglong2 b = r1[i]; wr.w1[2 * i] = b.x; wr.w1[2 * i + 1] = b.y;
        ulonglong2 c = r2[i]; wr.w2[2 * i] = c.x; wr.w2[2 * i + 1] = c.y;
    }
}

// Partial dot of this thread's k-quarter against its 3 weight rows.
__device__ __forceinline__ void dot3(const float* __restrict__ vpad, int s,
                                     const WReg& wr, float& s0, float& s1, float& s2) {
    const ulonglong2* hq = (const ulonglong2*)(vpad + QPAD * s);
    unsigned long long a0 = 0ull, a1 = 0ull, a2 = 0ull;
#pragma unroll
    for (int i = 0; i < 8; ++i) {
        ulonglong2 hv = hq[i];
        FFMA2(a0, hv.x, wr.w0[2 * i]); FFMA2(a0, hv.y, wr.w0[2 * i + 1]);
        FFMA2(a1, hv.x, wr.w1[2 * i]); FFMA2(a1, hv.y, wr.w1[2 * i + 1]);
        FFMA2(a2, hv.x, wr.w2[2 * i]); FFMA2(a2, hv.y, wr.w2[2 * i + 1]);
    }
    s0 = usum(a0); s1 = usum(a1); s2 = usum(a2);
}

__device__ __forceinline__ void reduce4(float& s0, float& s1, float& s2) {
    s0 += __shfl_xor_sync(0xffffffffu, s0, 1);
    s1 += __shfl_xor_sync(0xffffffffu, s1, 1);
    s2 += __shfl_xor_sync(0xffffffffu, s2, 1);
    s0 += __shfl_xor_sync(0xffffffffu, s0, 2);
    s1 += __shfl_xor_sync(0xffffffffu, s1, 2);
    s2 += __shfl_xor_sync(0xffffffffu, s2, 2);
}

// ---------------------------------------------------------------------------
// Kernel 1: input projections xp = x @ W_ih^T + b_ih (both directions).
// 148 CTAs x 512 threads; CTA = one direction, streams its row chunk.
// ---------------------------------------------------------------------------
__global__ __launch_bounds__(512, 1) void proj_kernel(
    const float* __restrict__ x,
    const float* __restrict__ Wf, const float* __restrict__ bf,
    const float* __restrict__ Wb, const float* __restrict__ bb)
{
    const int d = blockIdx.x / 74;   // 0 fwd, 1 bwd
    const int c = blockIdx.x % 74;
    const float* W  = d ? Wb : Wf;
    const float* bi = d ? bb : bf;
    const int tid = threadIdx.x;
    const int j3 = tid >> 2;
    const int s = tid & 3;

    WReg wr;
    load_weights(wr, W, j3, s, DX);
    const float bias = (s < 3) ? bi[3 * j3 + s] : 0.f;

    __shared__ __align__(16) float xs[2][4 * QPAD];

    const int chunk = (NROWS + 73) / 74;      // 1772
    const int r0 = c * chunk;
    const int r1 = min(r0 + chunk, NROWS);

    // row r -> b = r&31, t = r>>5 ; x is [B,T,Dx]
    float xr = 0.f;
    if (tid < DX) {
        int b0 = r0 & 31, t0 = r0 >> 5;
        xr = x[((size_t)(b0 * TT + t0)) * DX + tid];
    }
    const int pidx = (tid >> 5) * QPAD + (tid & 31);   // padded slot for tid<128
    int p = 0;
    for (int r = r0; r < r1; ++r) {
        if (tid < DX) {
            xs[p][pidx] = xr;
            if (r + 1 < r1) {
                int bn = (r + 1) & 31, tn = (r + 1) >> 5;
                xr = x[((size_t)(bn * TT + tn)) * DX + tid];
            }
        }
        __syncthreads();
        float s0, s1, s2;
        dot3(xs[p], s, wr, s0, s1, s2);
        if (s == 0) s0 += bias; else if (s == 1) s1 += bias; else if (s == 2) s2 += bias;
        reduce4(s0, s1, s2);
        if (s == 0) {
            float* o = g_xp + (size_t)r * 768 + d * GG + 3 * j3;
            o[0] = s0; o[1] = s1; o[2] = s2;
        }
        p ^= 1;
    }
}

// ---------------------------------------------------------------------------
// Kernel 2: sequential GRU scan. One CTA (512 thr) per (direction, batch).
// ---------------------------------------------------------------------------
__global__ __launch_bounds__(512, 1) void scan_kernel(
    const float* __restrict__ Whf, const float* __restrict__ bhf,
    const float* __restrict__ Whb, const float* __restrict__ bhb)
{
    const int bx = blockIdx.x;          // 64
    const int d = bx >> 5;
    const int b = bx & 31;
    const float* W  = d ? Whb : Whf;
    const float* bh = d ? bhb : bhf;
    const int tid = threadIdx.x;
    const int j3 = tid >> 2;
    const int s = tid & 3;
    const int o = 3 * j3 + s;           // this lane's "extra" output (s<3)

    WReg wr;
    load_weights(wr, W, j3, s, HH);
    const float bias  = (s < 3) ? bh[o] : 0.f;
    const bool  add_x = (s < 3) && (o < 2 * HH);   // r,z gates: x added pre-act
    const bool  is_n  = (s < 3) && (o >= 2 * HH);  // n gate: x stashed

    __shared__ __align__(16) float h_pad[4 * QPAD];
    __shared__ float ga[GG];
    __shared__ float xn_sh[HH];

    if (tid < 4 * QPAD) h_pad[tid] = 0.f;
    __syncthreads();

    const int stride = BB * 768;                       // floats per timestep
    const int t0 = d ? (TT - 1) : 0;
    const int dstep = d ? -stride : stride;
    const float* xptr = g_xp + (size_t)(t0 * BB + b) * 768 + d * GG + o;

    // depth-2 prefetch of this lane's x-projection value
    float xv = 0.f, xv2 = 0.f;
    if (s < 3) { xv = __ldg(xptr); xv2 = __ldg(xptr + dstep); }
    xptr += 2 * dstep;

    float* hout = g_h + (size_t)(b * TT) * 256 + d * HH + tid;  // tid<128
    const int hslot = (tid >> 5) * QPAD + (tid & 31);

    for (int tt = 0; tt < TT; ++tt) {
        const float xg = xv;
        xv = xv2;
        if (s < 3 && tt + 2 < TT) xv2 = __ldg(xptr);
        xptr += dstep;

        float s0, s1, s2;
        dot3(h_pad, s, wr, s0, s1, s2);
        const float ex = bias + (add_x ? xg : 0.f);
        if (s == 0) s0 += ex; else if (s == 1) s1 += ex; else if (s == 2) s2 += ex;
        reduce4(s0, s1, s2);
        if (s == 0) {
            ga[3 * j3] = s0; ga[3 * j3 + 1] = s1; ga[3 * j3 + 2] = s2;
        }
        if (is_n) xn_sh[o - 2 * HH] = xg;
        __syncthreads();

        if (tid < HH) {
            const float r = 1.f / (1.f + __expf(-ga[tid]));
            const float z = 1.f / (1.f + __expf(-ga[HH + tid]));
            const float npre = xn_sh[tid] + r * ga[2 * HH + tid];
            const float e = __expf(2.f * npre);        // tanh = 1 - 2/(e+1)
            const float n = 1.f - __fdividef(2.f, e + 1.f);
            const float hold = h_pad[hslot];
            const float hnew = n + z * (hold - n);     // (1-z)n + z h
            h_pad[hslot] = hnew;
            const int tcur = d ? (TT - 1 - tt) : tt;
            hout[(size_t)tcur * 256] = hnew;
        }
        __syncthreads();
    }
}

// ---------------------------------------------------------------------------
// Kernel 3: FC head out = hcat @ Wfc^T + bfc. Warp per row, memory-bound.
// ---------------------------------------------------------------------------
__global__ __launch_bounds__(256) void fc_kernel(
    const float* __restrict__ Wfc, const float* __restrict__ bfc,
    float* __restrict__ out)
{
    __shared__ float Ws[NK * 256];
    __shared__ float bs[NK];
    for (int i = threadIdx.x; i < NK * 256; i += 256) Ws[i] = Wfc[i];
    if (threadIdx.x < NK) bs[threadIdx.x] = bfc[threadIdx.x];
    __syncthreads();

    const int gwarp = (blockIdx.x * 256 + threadIdx.x) >> 5;
    const int lane = threadIdx.x & 31;
    const int nwarps = gridDim.x * 8;

    for (int row = gwarp; row < NROWS; row += nwarps) {
        const float* hr = g_h + (size_t)row * 256;
        float hv[8];
#pragma unroll
        for (int m = 0; m < 8; ++m) hv[m] = hr[lane + 32 * m];
        float acc[NK];
#pragma unroll
        for (int k = 0; k < NK; ++k) {
            float sAcc = 0.f;
#pragma unroll
            for (int m = 0; m < 8; ++m) sAcc += hv[m] * Ws[k * 256 + lane + 32 * m];
            acc[k] = sAcc;
        }
#pragma unroll
        for (int k = 0; k < NK; ++k) {
#pragma unroll
            for (int off = 16; off > 0; off >>= 1)
                acc[k] += __shfl_down_sync(0xffffffffu, acc[k], off);
        }
        if (lane == 0) {
#pragma unroll
            for (int k = 0; k < NK; ++k)
                out[(size_t)row * NK + k] = acc[k] + bs[k];
        }
    }
}

// ---------------------------------------------------------------------------
extern "C" void kernel_launch(void* const* d_in, const int* in_sizes, int n_in,
                              void* d_out, int out_size)
{
    const float* x    = (const float*)d_in[0];
    const float* Wihf = (const float*)d_in[1];
    const float* Whhf = (const float*)d_in[2];
    const float* bihf = (const float*)d_in[3];
    const float* bhhf = (const float*)d_in[4];
    const float* Wihb = (const float*)d_in[5];
    const float* Whhb = (const float*)d_in[6];
    const float* bihb = (const float*)d_in[7];
    const float* bhhb = (const float*)d_in[8];
    const float* Wfc  = (const float*)d_in[9];
    const float* bfc  = (const float*)d_in[10];
    float* out = (float*)d_out;

    proj_kernel<<<148, 512>>>(x, Wihf, bihf, Wihb, bihb);
    scan_kernel<<<64, 512>>>(Whhf, bhhf, Whhb, bhhb);
    fc_kernel<<<296, 256>>>(Wfc, bfc, out);
}

// round 4
// speedup vs baseline: 1.1653x; 1.0653x over previous
#include <cuda_runtime.h>

#define BB 32
#define TT 4096
#define DX 128
#define HH 128
#define GG 384       // 3*H
#define NK 10
#define NROWS (BB*TT)   // 131072

// Scratch: input projections [t*B+b][768] (fwd gates 0..383, bwd 384..767)
// gate-major within a direction: [gate*128 + j]
__device__ float g_xp[(size_t)NROWS * 768];
// Hidden states concatenated [b*T+t][256] (fwd 0..127, bwd 128..255)
__device__ float g_h[(size_t)NROWS * 256];

// Packed dual fp32 FMA (sm_103a): d.lo += a.lo*b.lo ; d.hi += a.hi*b.hi
#define FFMA2(acc, aa, bb) \
    asm("fma.rn.f32x2 %0, %1, %2, %0;" : "+l"(acc) : "l"(aa), "l"(bb))

__device__ __forceinline__ float f_lo(unsigned long long v) { return __uint_as_float((unsigned)v); }
__device__ __forceinline__ float f_hi(unsigned long long v) { return __uint_as_float((unsigned)(v >> 32)); }
__device__ __forceinline__ float usum(unsigned long long v) { return f_lo(v) + f_hi(v); }

// Padded vector layout: k-quarter s (32 floats) at float offset 36*s ->
// quarter bases hit banks {0,4,8,12}: the 4 s-groups of a warp read disjoint
// bank sets; every LDS.128 is conflict-free.
#define QPAD 36

// Thread (j = tid>>2, s = tid&3), 512 threads. Outputs r_j, z_j, n_j
// (W rows j, 128+j, 256+j), k-quarter s. 96 weight regs/thread.
struct WReg { unsigned long long w0[16], w1[16], w2[16]; };

__device__ __forceinline__ void load_weights(WReg& wr, const float* __restrict__ W,
                                             int j, int s, int ldw) {
    const ulonglong2* r0 = (const ulonglong2*)(W + (j)       * ldw + 32 * s);
    const ulonglong2* r1 = (const ulonglong2*)(W + (128 + j) * ldw + 32 * s);
    const ulonglong2* r2 = (const ulonglong2*)(W + (256 + j) * ldw + 32 * s);
#pragma unroll
    for (int i = 0; i < 8; ++i) {
        ulonglong2 a = r0[i]; wr.w0[2 * i] = a.x; wr.w0[2 * i + 1] = a.y;
        ulonglong2 b = r1[i]; wr.w1[2 * i] = b.x; wr.w1[2 * i + 1] = b.y;
        ulonglong2 c = r2[i]; wr.w2[2 * i] = c.x; wr.w2[2 * i + 1] = c.y;
    }
}

// Partial dot of this thread's k-quarter against its 3 weight rows.
__device__ __forceinline__ void dot3(const float* __restrict__ vpad, int s,
                                     const WReg& wr, float& s0, float& s1, float& s2) {
    const ulonglong2* hq = (const ulonglong2*)(vpad + QPAD * s);
    unsigned long long a0 = 0ull, a1 = 0ull, a2 = 0ull;
#pragma unroll
    for (int i = 0; i < 8; ++i) {
        ulonglong2 hv = hq[i];
        FFMA2(a0, hv.x, wr.w0[2 * i]); FFMA2(a0, hv.y, wr.w0[2 * i + 1]);
        FFMA2(a1, hv.x, wr.w1[2 * i]); FFMA2(a1, hv.y, wr.w1[2 * i + 1]);
        FFMA2(a2, hv.x, wr.w2[2 * i]); FFMA2(a2, hv.y, wr.w2[2 * i + 1]);
    }
    s0 = usum(a0); s1 = usum(a1); s2 = usum(a2);
}

// Butterfly k-reduction over the 4-lane group: all lanes end with full sums.
__device__ __forceinline__ void bfly3(float& a, float& b, float& c) {
    a += __shfl_xor_sync(0xffffffffu, a, 1);
    b += __shfl_xor_sync(0xffffffffu, b, 1);
    c += __shfl_xor_sync(0xffffffffu, c, 1);
    a += __shfl_xor_sync(0xffffffffu, a, 2);
    b += __shfl_xor_sync(0xffffffffu, b, 2);
    c += __shfl_xor_sync(0xffffffffu, c, 2);
}

// ---------------------------------------------------------------------------
// Kernel 1: input projections xp = x @ W_ih^T + b_ih (both directions).
// 148 CTAs x 512 threads; 4-row tiles per barrier, double-buffered SMEM.
// ---------------------------------------------------------------------------
__global__ __launch_bounds__(512, 1) void proj_kernel(
    const float* __restrict__ x,
    const float* __restrict__ Wf, const float* __restrict__ bf,
    const float* __restrict__ Wb, const float* __restrict__ bb)
{
    const int d = blockIdx.x / 74;   // 0 fwd, 1 bwd
    const int c = blockIdx.x % 74;
    const float* W  = d ? Wb : Wf;
    const float* bi = d ? bb : bf;
    const int tid = threadIdx.x;
    const int j = tid >> 2;
    const int s = tid & 3;

    WReg wr;
    load_weights(wr, W, j, s, DX);
    const float bias = (s < 3) ? bi[s * 128 + j] : 0.f;

    __shared__ __align__(16) float xs[2][4][4 * QPAD];

    const int chunk = (NROWS + 73) / 74;      // 1772 (div by 4)
    const int r0 = c * chunk;
    const int r1 = min(r0 + chunk, NROWS);

    // load role: row-in-tile rt, element e  (row r -> b=r&31, t=r>>5)
    const int rt = tid >> 7;
    const int e = tid & 127;
    const int lslot = (e >> 5) * QPAD + (e & 31);

    int rb0 = (r0 + rt) & 31, rt0 = (r0 + rt) >> 5;
    float xr = __ldg(x + ((size_t)(rb0 * TT + rt0)) * DX + e);

    int p = 0;
    for (int r = r0; r < r1; r += 4) {
        xs[p][rt][lslot] = xr;
        __syncthreads();
        if (r + 4 < r1) {
            int bn = (r + 4 + rt) & 31, tn = (r + 4 + rt) >> 5;
            xr = __ldg(x + ((size_t)(bn * TT + tn)) * DX + e);
        }
#pragma unroll
        for (int q = 0; q < 4; ++q) {
            float d0, d1, d2;
            dot3(xs[p][q], s, wr, d0, d1, d2);
            if (s == 0) d0 += bias; else if (s == 1) d1 += bias; else if (s == 2) d2 += bias;
            bfly3(d0, d1, d2);
            if (s < 3) {
                const float outv = (s == 0) ? d0 : ((s == 1) ? d1 : d2);
                g_xp[(size_t)(r + q) * 768 + d * GG + s * 128 + j] = outv;
            }
        }
        p ^= 1;
    }
}

// ---------------------------------------------------------------------------
// Kernel 2: sequential GRU scan. One CTA (512 thr) per (direction, batch).
// ONE barrier per step: lane s==0 of each 4-group owns dim j end-to-end
// (pre-acts -> nonlinearity -> h update), h double-buffered in SMEM,
// h_prev kept in a register.
// ---------------------------------------------------------------------------
__global__ __launch_bounds__(512, 1) void scan_kernel(
    const float* __restrict__ Whf, const float* __restrict__ bhf,
    const float* __restrict__ Whb, const float* __restrict__ bhb)
{
    const int bx = blockIdx.x;          // 64
    const int d = bx >> 5;
    const int b = bx & 31;
    const float* W  = d ? Whb : Whf;
    const float* bh = d ? bhb : bhf;
    const int tid = threadIdx.x;
    const int j = tid >> 2;
    const int s = tid & 3;
    const int lane = tid & 31;

    WReg wr;
    load_weights(wr, W, j, s, HH);
    const float bias = (s < 3) ? bh[s * 128 + j] : 0.f;

    __shared__ __align__(16) float h_pad[2][4 * QPAD];
    if (tid < 4 * QPAD) h_pad[0][tid] = 0.f;
    __syncthreads();

    const int stride = BB * 768;                       // floats per timestep
    const int t0 = d ? (TT - 1) : 0;
    const int dstep = d ? -stride : stride;
    const bool ldx = (s != 2);
    // lane's x element: s0 -> xr_j, s1 -> xz_j, s3 -> xn_j
    const int xoff = d * GG + ((s == 3) ? (256 + j) : (s * 128 + j));
    const float* xptr = g_xp + (size_t)(t0 * BB + b) * 768 + xoff;

    float xv = 0.f, xv2 = 0.f;
    if (ldx) { xv = __ldg(xptr); xv2 = __ldg(xptr + dstep); }
    xptr += 2 * dstep;

    float hprev = 0.f;
    float* hout = g_h + (size_t)(b * TT) * 256 + d * HH + j;  // lane s==0 writes
    const int slot = (j >> 5) * QPAD + (j & 31);

    int p = 0;
    for (int tt = 0; tt < TT; ++tt) {
        const float xg = xv;
        xv = xv2;
        if (ldx && tt + 2 < TT) xv2 = __ldg(xptr);
        xptr += dstep;

        float d0, d1, d2;
        dot3(h_pad[p], s, wr, d0, d1, d2);
        const float c = bias + ((s < 2) ? xg : 0.f);
        if (s == 0) d0 += c; else if (s == 1) d1 += c; else if (s == 2) d2 += c;
        bfly3(d0, d1, d2);
        const float xn = __shfl_sync(0xffffffffu, xg, lane | 3);

        if (s == 0) {
            const float r = 1.f / (1.f + __expf(-d0));
            const float z = 1.f / (1.f + __expf(-d1));
            const float npre = xn + r * d2;
            const float e2 = __expf(2.f * npre);       // tanh = 1 - 2/(e+1)
            const float n = 1.f - __fdividef(2.f, e2 + 1.f);
            const float hnew = n + z * (hprev - n);    // (1-z)n + z h
            hprev = hnew;
            h_pad[p ^ 1][slot] = hnew;
            const int tcur = d ? (TT - 1 - tt) : tt;
            hout[(size_t)tcur * 256] = hnew;
        }
        __syncthreads();
        p ^= 1;
    }
}

// ---------------------------------------------------------------------------
// Kernel 3: FC head out = hcat @ Wfc^T + bfc. Warp per row, memory-bound.
// ---------------------------------------------------------------------------
__global__ __launch_bounds__(256) void fc_kernel(
    const float* __restrict__ Wfc, const float* __restrict__ bfc,
    float* __restrict__ out)
{
    __shared__ float Ws[NK * 256];
    __shared__ float bs[NK];
    for (int i = threadIdx.x; i < NK * 256; i += 256) Ws[i] = Wfc[i];
    if (threadIdx.x < NK) bs[threadIdx.x] = bfc[threadIdx.x];
    __syncthreads();

    const int gwarp = (blockIdx.x * 256 + threadIdx.x) >> 5;
    const int lane = threadIdx.x & 31;
    const int nwarps = gridDim.x * 8;

    for (int row = gwarp; row < NROWS; row += nwarps) {
        const float* hr = g_h + (size_t)row * 256;
        float hv[8];
#pragma unroll
        for (int m = 0; m < 8; ++m) hv[m] = hr[lane + 32 * m];
        float acc[NK];
#pragma unroll
        for (int k = 0; k < NK; ++k) {
            float sAcc = 0.f;
#pragma unroll
            for (int m = 0; m < 8; ++m) sAcc += hv[m] * Ws[k * 256 + lane + 32 * m];
            acc[k] = sAcc;
        }
#pragma unroll
        for (int k = 0; k < NK; ++k) {
#pragma unroll
            for (int off = 16; off > 0; off >>= 1)
                acc[k] += __shfl_down_sync(0xffffffffu, acc[k], off);
        }
        if (lane == 0) {
#pragma unroll
            for (int k = 0; k < NK; ++k)
                out[(size_t)row * NK + k] = acc[k] + bs[k];
        }
    }
}

// ---------------------------------------------------------------------------
extern "C" void kernel_launch(void* const* d_in, const int* in_sizes, int n_in,
                              void* d_out, int out_size)
{
    const float* x    = (const float*)d_in[0];
    const float* Wihf = (const float*)d_in[1];
    const float* Whhf = (const float*)d_in[2];
    const float* bihf = (const float*)d_in[3];
    const float* bhhf = (const float*)d_in[4];
    const float* Wihb = (const float*)d_in[5];
    const float* Whhb = (const float*)d_in[6];
    const float* bihb = (const float*)d_in[7];
    const float* bhhb = (const float*)d_in[8];
    const float* Wfc  = (const float*)d_in[9];
    const float* bfc  = (const float*)d_in[10];
    float* out = (float*)d_out;

    proj_kernel<<<148, 512>>>(x, Wihf, bihf, Wihb, bihb);
    scan_kernel<<<64, 512>>>(Whhf, bhhf, Whhb, bhhb);
    fc_kernel<<<296, 256>>>(Wfc, bfc, out);
}